// round 2
// baseline (speedup 1.0000x reference)
#include <cuda_runtime.h>

// Problem sizes (fixed by the reference)
#define NTN 500000   // transaction nodes
#define NCN 100000   // client nodes
#define NMN 20000    // merchant nodes
#define NE  500000   // edges per relation
#define FIN 128      // transaction feature dim
#define FHID 64

// ---------------- device scratch (allocation-free) ----------------
__device__ float g_agg_c[NCN * FIN];   // sum of feat[src] per client dst (t2c)
__device__ float g_agg_m[NMN * FIN];   // sum of feat[src] per merchant dst (t2m)
__device__ float g_p_c[NCN * 2];       // fused lrelu(h0_c) @ (W1_c2t@Wf) + b1@Wf
__device__ float g_p_m[NMN * 2];
__device__ int   g_cnt_t2c[NCN];
__device__ int   g_cnt_t2m[NMN];
__device__ int   g_cnt_c2t[NTN];
__device__ int   g_cnt_m2t[NTN];
__device__ float g_M_c[FHID * 2];      // W1_c2t @ Wf
__device__ float g_M_m[FHID * 2];      // W1_m2t @ Wf
__device__ float g_b2_c[2];            // b1_c2t @ Wf
__device__ float g_b2_m[2];            // b1_m2t @ Wf

// ---------------- kernels ----------------

__global__ void zero_kernel() {
    int i = blockIdx.x * blockDim.x + threadIdx.x;
    int stride = gridDim.x * blockDim.x;
    float4 z = make_float4(0.f, 0.f, 0.f, 0.f);
    float4* a = (float4*)g_agg_c;
    for (int j = i; j < NCN * FIN / 4; j += stride) a[j] = z;
    float4* b = (float4*)g_agg_m;
    for (int j = i; j < NMN * FIN / 4; j += stride) b[j] = z;
    for (int j = i; j < NCN; j += stride) g_cnt_t2c[j] = 0;
    for (int j = i; j < NMN; j += stride) g_cnt_t2m[j] = 0;
    for (int j = i; j < NTN; j += stride) { g_cnt_c2t[j] = 0; g_cnt_m2t[j] = 0; }
}

template <int W>
__global__ void count_kernel(const int* __restrict__ dst) {
    int i = blockIdx.x * blockDim.x + threadIdx.x;
    if (i >= NE) return;
    int* cnt = (W == 0) ? g_cnt_t2c : (W == 1) ? g_cnt_t2m : (W == 2) ? g_cnt_c2t : g_cnt_m2t;
    atomicAdd(&cnt[dst[i]], 1);
}

// One warp per edge: gather one 512B feature row, vector-reduce into L2-resident agg.
template <int W>
__global__ void scatter_feat_kernel(const float* __restrict__ feat,
                                    const int* __restrict__ src,
                                    const int* __restrict__ dst) {
    int g = blockIdx.x * blockDim.x + threadIdx.x;
    int e = g >> 5;
    int lane = g & 31;
    if (e >= NE) return;
    float* agg = W ? g_agg_m : g_agg_c;
    int s = src[e];
    int d = dst[e];
    float4 v = __ldg((const float4*)feat + (size_t)s * (FIN / 4) + lane);
    float* ap = agg + (size_t)d * FIN + lane * 4;
    asm volatile("red.global.add.v4.f32 [%0], {%1,%2,%3,%4};"
                 :: "l"(ap), "f"(v.x), "f"(v.y), "f"(v.z), "f"(v.w) : "memory");
}

// Tiny: M = W1 @ Wf (64x2), b2 = b1 @ Wf for both needed relations. One block.
__global__ void make_M_kernel(const float* __restrict__ W1c, const float* __restrict__ b1c,
                              const float* __restrict__ W1m, const float* __restrict__ b1m,
                              const float* __restrict__ Wf) {
    int t = threadIdx.x;  // 256 threads
    if (t < 128) {
        int k = t >> 1, o = t & 1;
        float s = 0.f;
        #pragma unroll
        for (int j = 0; j < FHID; j++) s += W1c[k * FHID + j] * Wf[j * 2 + o];
        g_M_c[k * 2 + o] = s;
    } else {
        int tt = t - 128;
        int k = tt >> 1, o = tt & 1;
        float s = 0.f;
        #pragma unroll
        for (int j = 0; j < FHID; j++) s += W1m[k * FHID + j] * Wf[j * 2 + o];
        g_M_m[k * 2 + o] = s;
    }
    if (t < 2) {
        float s = 0.f;
        #pragma unroll
        for (int j = 0; j < FHID; j++) s += b1c[j] * Wf[j * 2 + t];
        g_b2_c[t] = s;
    } else if (t < 4) {
        int o = t - 2;
        float s = 0.f;
        #pragma unroll
        for (int j = 0; j < FHID; j++) s += b1m[j] * Wf[j * 2 + o];
        g_b2_m[o] = s;
    }
}

// Fused per-dst-node: h0 = lrelu( (agg/cnt)@W0 + b0 ) [0 if cnt==0],
// then p = h0 @ M + b2  (2 outputs per node).
// 128 threads, 16 nodes per block, 8 threads (= 8x8 cols) per node.
template <int W>
__global__ void layer0_kernel(const float* __restrict__ W0, const float* __restrict__ b0) {
    __shared__ float sW[FIN * FHID];          // 32 KB
    __shared__ float sA[16 * 129];            // padded stride 129 -> no bank conflicts

    const float* agg = W ? g_agg_m : g_agg_c;
    const int*   cnt = W ? g_cnt_t2m : g_cnt_t2c;
    const float* M   = W ? g_M_m : g_M_c;
    const float* b2  = W ? g_b2_m : g_b2_c;
    float*       pout = W ? g_p_m : g_p_c;

    int t = threadIdx.x;              // 0..127
    int base = blockIdx.x * 16;

    // load W0 (128x64) into smem
    float4* sW4w = (float4*)sW;
    const float4* W04 = (const float4*)W0;
    for (int i = t; i < FIN * FHID / 4; i += 128) sW4w[i] = W04[i];
    // load 16 agg rows
    for (int i = t; i < 16 * FIN; i += 128) {
        int n = i >> 7, k = i & 127;
        sA[n * 129 + k] = agg[(size_t)(base + n) * FIN + k];
    }
    __syncthreads();

    int n = t >> 3;        // node within block
    int cg = t & 7;        // column group: cols [cg*8, cg*8+8)
    float acc[8] = {0.f, 0.f, 0.f, 0.f, 0.f, 0.f, 0.f, 0.f};
    const float4* sW4 = (const float4*)sW;
    #pragma unroll 4
    for (int k = 0; k < FIN; k++) {
        float a = sA[n * 129 + k];
        float4 w0 = sW4[k * 16 + cg * 2];
        float4 w1 = sW4[k * 16 + cg * 2 + 1];
        acc[0] += a * w0.x; acc[1] += a * w0.y; acc[2] += a * w0.z; acc[3] += a * w0.w;
        acc[4] += a * w1.x; acc[5] += a * w1.y; acc[6] += a * w1.z; acc[7] += a * w1.w;
    }

    int node = base + n;
    int c = cnt[node];
    float p0 = 0.f, p1 = 0.f;
    if (c > 0) {
        float inv = 1.f / (float)c;
        #pragma unroll
        for (int j = 0; j < 8; j++) {
            int col = cg * 8 + j;
            float h = acc[j] * inv + b0[col];
            h = (h > 0.f) ? h : 0.01f * h;        // leaky_relu
            p0 += h * M[col * 2];
            p1 += h * M[col * 2 + 1];
        }
    }
    // reduce over the 8 threads that own this node's columns
    #pragma unroll
    for (int off = 4; off; off >>= 1) {
        p0 += __shfl_down_sync(0xffffffffu, p0, off, 8);
        p1 += __shfl_down_sync(0xffffffffu, p1, off, 8);
    }
    if (cg == 0) {
        pout[node * 2]     = p0 + b2[0];
        pout[node * 2 + 1] = p1 + b2[1];
    }
}

__global__ void out_init_kernel(float* __restrict__ out, const float* __restrict__ bf) {
    int i = blockIdx.x * blockDim.x + threadIdx.x;
    if (i < NTN) ((float2*)out)[i] = make_float2(bf[0], bf[1]);
}

// Final scatter: out[dst] += p[src] / cnt[dst]  (2-wide vector reduction)
template <int W>
__global__ void scatter_out_kernel(const int* __restrict__ src, const int* __restrict__ dst,
                                   float* __restrict__ out) {
    int e = blockIdx.x * blockDim.x + threadIdx.x;
    if (e >= NE) return;
    int s = src[e], d = dst[e];
    const float* p   = W ? g_p_m : g_p_c;
    const int*   cnt = W ? g_cnt_m2t : g_cnt_c2t;
    float inv = 1.f / (float)cnt[d];
    float a = p[2 * s] * inv;
    float b = p[2 * s + 1] * inv;
    float* ap = out + 2 * (size_t)d;
    asm volatile("red.global.add.v2.f32 [%0], {%1,%2};"
                 :: "l"(ap), "f"(a), "f"(b) : "memory");
}

// ---------------- launch ----------------
extern "C" void kernel_launch(void* const* d_in, const int* in_sizes, int n_in,
                              void* d_out, int out_size) {
    const float* feat    = (const float*)d_in[0];
    const int* src_c2t   = (const int*)d_in[3];
    const int* dst_c2t   = (const int*)d_in[4];
    const int* src_m2t   = (const int*)d_in[5];
    const int* dst_m2t   = (const int*)d_in[6];
    const int* src_t2c   = (const int*)d_in[7];
    const int* dst_t2c   = (const int*)d_in[8];
    const int* src_t2m   = (const int*)d_in[9];
    const int* dst_t2m   = (const int*)d_in[10];
    const float* W1_c2t  = (const float*)d_in[13];
    const float* b1_c2t  = (const float*)d_in[14];
    const float* W1_m2t  = (const float*)d_in[17];
    const float* b1_m2t  = (const float*)d_in[18];
    const float* W0_t2c  = (const float*)d_in[19];
    const float* b0_t2c  = (const float*)d_in[20];
    const float* W0_t2m  = (const float*)d_in[23];
    const float* b0_t2m  = (const float*)d_in[24];
    const float* Wf      = (const float*)d_in[27];
    const float* bf      = (const float*)d_in[28];
    float* out = (float*)d_out;

    const int TB = 256;
    zero_kernel<<<4096, TB>>>();
    count_kernel<0><<<(NE + TB - 1) / TB, TB>>>(dst_t2c);
    count_kernel<1><<<(NE + TB - 1) / TB, TB>>>(dst_t2m);
    count_kernel<2><<<(NE + TB - 1) / TB, TB>>>(dst_c2t);
    count_kernel<3><<<(NE + TB - 1) / TB, TB>>>(dst_m2t);
    make_M_kernel<<<1, 256>>>(W1_c2t, b1_c2t, W1_m2t, b1_m2t, Wf);

    // layer-0 aggregation: 1 warp/edge -> NE*32 threads
    scatter_feat_kernel<0><<<NE * 32 / TB, TB>>>(feat, src_t2c, dst_t2c);
    scatter_feat_kernel<1><<<NE * 32 / TB, TB>>>(feat, src_t2m, dst_t2m);

    // fused dst-side transform + lrelu + (W1@Wf) projection
    layer0_kernel<0><<<NCN / 16, 128>>>(W0_t2c, b0_t2c);
    layer0_kernel<1><<<NMN / 16, 128>>>(W0_t2m, b0_t2m);

    // output = bf + mean-scatter of 2-wide projected messages
    out_init_kernel<<<(NTN + TB - 1) / TB, TB>>>(out, bf);
    scatter_out_kernel<0><<<(NE + TB - 1) / TB, TB>>>(src_c2t, dst_c2t, out);
    scatter_out_kernel<1><<<(NE + TB - 1) / TB, TB>>>(src_m2t, dst_m2t, out);
}